// round 8
// baseline (speedup 1.0000x reference)
#include <cuda_runtime.h>

// ---------------- problem constants (fixed by dataset) ----------------
#define NPIX 147456        // 384*384
#define W384 384
#define NNZC 1474560       // NPIX/2 * 20  == NPIX * 10
#define NLOC 73728         // NPIX/2
#define KIU  5
#define CG_STEPS 30
#define EPT  10            // COO entries per thread (NNZC / NPIX exactly)

#define TPB   512
#define NBLK  288          // 288*512 == NPIX exactly
#define MPB   256          // matting pixels per block (NLOC / NBLK)
#define NWARP (TPB / 32)
#define EPB   (NNZC / NBLK)   // COO entries per block in setup = 5120

// ---------------- device scratch (static only) ----------------
// transposed entry streams: element j of thread t lives at [j*NPIX + t]
__device__ int2  g_pairRT[NNZC];       // CSR-sorted {col, val-bits}
__device__ int   g_ridRT[NNZC];        // CSR-sorted row ids
__device__ int2  g_pairCT[NNZC];       // CSC-sorted {row, val-bits}
__device__ int   g_cidCT[NNZC];        // CSC-sorted col ids
__device__ int   g_ptrR[NPIX + 1];
__device__ int   g_ptrC[NPIX + 1];
__device__ int   g_cntR[NPIX];
__device__ int   g_cntC[NPIX];
__device__ int   g_tmpR[NPIX];
__device__ int   g_tmpC[NPIX];
__device__ int2  g_btot2[NBLK];

__device__ float g_rs_cm[NPIX];
__device__ float g_D[NPIX];
__device__ float g_S45[45 * NLOC];     // symmetric matting blocks [t*NLOC + k]
__device__ float g_Wiu[KIU * NLOC];    // [l*NLOC + k]
__device__ int   g_iuNbT[KIU * NLOC];  // transposed neighbor indices
__device__ float g_r[NPIX];
__device__ float g_w[NPIX];            // accumulates A*r (zeroed each iter)
__device__ float2 g_LA[NPIX];          // {rs*r, sum(val*r)} -> Lv = x - y
__device__ double2 g_dot1[NBLK];       // {gamma, delta partial from P1}
__device__ double  g_dot2[NBLK];       // delta partials from P2

__device__ unsigned g_count;
__device__ volatile unsigned g_sense;
__device__ unsigned g_exit;

// ---------------- helpers ----------------
__device__ __forceinline__ int OFF9(int i) {
    int a = i / 3, b = i % 3;
    return (a - 1) + (b - 1) * W384;
}
__device__ __forceinline__ int TIDX(int i, int j) {
    return 9 * i - (i * (i - 1)) / 2 + (j - i);
}

__device__ __forceinline__ double bred(double v, double* sm) {
    int lane = threadIdx.x & 31, w = threadIdx.x >> 5;
    #pragma unroll
    for (int o = 16; o > 0; o >>= 1) v += __shfl_down_sync(0xffffffffu, v, o);
    if (lane == 0) sm[w] = v;
    __syncthreads();
    if (w == 0) {
        v = (lane < NWARP) ? sm[lane] : 0.0;
        #pragma unroll
        for (int o = 8; o > 0; o >>= 1) v += __shfl_down_sync(0xffffu, v, o);
    }
    __syncthreads();
    return v; // valid on thread 0
}

__device__ __forceinline__ double2 bred2(double a, double b, double2* sm2) {
    int lane = threadIdx.x & 31, w = threadIdx.x >> 5;
    #pragma unroll
    for (int o = 16; o > 0; o >>= 1) {
        a += __shfl_down_sync(0xffffffffu, a, o);
        b += __shfl_down_sync(0xffffffffu, b, o);
    }
    if (lane == 0) sm2[w] = make_double2(a, b);
    __syncthreads();
    if (w == 0) {
        double2 t = (lane < NWARP) ? sm2[lane] : make_double2(0.0, 0.0);
        a = t.x; b = t.y;
        #pragma unroll
        for (int o = 8; o > 0; o >>= 1) {
            a += __shfl_down_sync(0xffffu, a, o);
            b += __shfl_down_sync(0xffffu, b, o);
        }
    }
    __syncthreads();
    return make_double2(a, b);
}

// single-counter sense barrier (g_count self-resets; g_sense reset at exit)
__device__ __forceinline__ void gbar(unsigned &ep) {
    ep++;
    __syncthreads();
    if (threadIdx.x == 0) {
        __threadfence();
        if (atomicAdd(&g_count, 1u) == NBLK - 1) {
            g_count = 0;
            __threadfence();
            g_sense = ep;
        } else {
            while (g_sense != ep) { __nanosleep(32); }
            __threadfence();
        }
    }
    __syncthreads();
}

// ---------------- single persistent kernel: setup + CG ----------------
__global__ void __launch_bounds__(TPB, 2) k_all(
    float* __restrict__ x,
    const float* __restrict__ CMw,  const float* __restrict__ LOCw,
    const float* __restrict__ IUw,  const float* __restrict__ KUw,
    const float* __restrict__ lmbda,
    const float* __restrict__ kToUcf, const float* __restrict__ known,
    const float* __restrict__ kToU, const float* __restrict__ Wd,
    const float* __restrict__ LF,   const float* __restrict__ IUf,
    const int* __restrict__ wrow,   const int* __restrict__ wcol,
    const int* __restrict__ locInd, const int* __restrict__ iuInd,
    const int* __restrict__ iuNb)
{
    __shared__ int2   s_scan[TPB];
    __shared__ double2 sm2[NWARP];
    __shared__ double sred[NWARP];
    __shared__ int2   s_off;
    __shared__ double s_alpha, s_beta, s_gamma_prev, s_alpha_prev;

    const int tid  = threadIdx.x;
    const int gtid = blockIdx.x * TPB + tid;     // always < NPIX
    const int m    = blockIdx.x * MPB + tid;     // matting pixel if tid < MPB
    const int ebase = blockIdx.x * EPB;
    unsigned ep = 0;

    // ---- P0: zero working state
    g_cntR[gtid] = 0; g_cntC[gtid] = 0; g_tmpR[gtid] = 0; g_tmpC[gtid] = 0;
    g_rs_cm[gtid] = 0.f; g_D[gtid] = 0.f;
    g_w[gtid] = 0.f; g_LA[gtid] = make_float2(0.f, 0.f);
    gbar(ep);

    // ---- S1: COO counts + rowsums, plus precompute (matting, IU, data term)
    for (int e = tid; e < EPB; e += TPB) {
        int k = ebase + e;
        int r = wrow[k], c = wcol[k];
        float cv = CMw[r] * Wd[k];
        atomicAdd(&g_rs_cm[r], cv);
        atomicAdd(&g_cntR[r], 1);
        atomicAdd(&g_cntC[c], 1);
    }
    float r_reg;
    {
        float dk = KUw[gtid] * kToUcf[gtid] + lmbda[0] * known[gtid];
        r_reg = dk * kToU[gtid];
        g_r[gtid] = r_reg;
        atomicAdd(&g_D[gtid], dk);
    }
    if (tid < MPB) {
        // matting symmetric blocks
        {
            int ind = locInd[m];
            float w = LOCw[ind];
            float rs[9];
            #pragma unroll
            for (int q = 0; q < 9; q++) rs[q] = 0.f;
            #pragma unroll
            for (int a = 0; a < 9; a++) {
                #pragma unroll
                for (int b2 = a; b2 < 9; b2++) {
                    float s = 0.5f * w * (LF[(b2 * 9 + a) * NLOC + m] + LF[(a * 9 + b2) * NLOC + m]);
                    g_S45[TIDX(a, b2) * NLOC + m] = s;
                    rs[a] += s;
                    if (b2 > a) rs[b2] += s;
                }
            }
            #pragma unroll
            for (int q = 0; q < 9; q++) atomicAdd(&g_D[ind + OFF9(q)], rs[q]);
        }
        // IU weights
        {
            int ind = iuInd[m];
            float w = IUw[ind];
            #pragma unroll
            for (int l = 0; l < KIU; l++) {
                float wv = 0.5f * w * IUf[m * KIU + l];
                int nb = iuNb[m * KIU + l];
                g_Wiu[l * NLOC + m] = wv;
                g_iuNbT[l * NLOC + m] = nb;
                atomicAdd(&g_D[ind], wv);
                atomicAdd(&g_D[nb], wv);
            }
        }
    }
    gbar(ep);

    // ---- S2: block-local inclusive scan of {cntR, cntC}
    int2 myc = make_int2(g_cntR[gtid], g_cntC[gtid]);
    s_scan[tid] = myc;
    __syncthreads();
    for (int o = 1; o < TPB; o <<= 1) {
        int2 t = (tid >= o) ? s_scan[tid - o] : make_int2(0, 0);
        __syncthreads();
        s_scan[tid].x += t.x;
        s_scan[tid].y += t.y;
        __syncthreads();
    }
    int2 incl = s_scan[tid];
    int exR = incl.x - myc.x, exC = incl.y - myc.y;
    if (tid == TPB - 1) g_btot2[blockIdx.x] = incl;
    gbar(ep);

    // ---- S3: block offsets + write ptr arrays
    {
        int2 v = (tid < blockIdx.x) ? g_btot2[tid] : make_int2(0, 0);
        int lane = tid & 31, w = tid >> 5;
        #pragma unroll
        for (int o = 16; o > 0; o >>= 1) {
            v.x += __shfl_down_sync(0xffffffffu, v.x, o);
            v.y += __shfl_down_sync(0xffffffffu, v.y, o);
        }
        __shared__ int2 sw[NWARP];
        if (lane == 0) sw[w] = v;
        __syncthreads();
        if (w == 0) {
            int2 t = (lane < NWARP) ? sw[lane] : make_int2(0, 0);
            #pragma unroll
            for (int o = 8; o > 0; o >>= 1) {
                t.x += __shfl_down_sync(0xffffu, t.x, o);
                t.y += __shfl_down_sync(0xffffu, t.y, o);
            }
            if (lane == 0) s_off = t;
        }
        __syncthreads();
        g_ptrR[gtid] = exR + s_off.x;
        g_ptrC[gtid] = exC + s_off.y;
        if (gtid == 0) { g_ptrR[NPIX] = NNZC; g_ptrC[NPIX] = NNZC; }
    }
    gbar(ep);

    // ---- S4: scatter into transposed CSR/CSC entry streams
    for (int e = tid; e < EPB; e += TPB) {
        int k = ebase + e;
        int r = wrow[k], c = wcol[k];
        int vb = __float_as_int(CMw[r] * Wd[k]);
        int p1 = g_ptrR[r] + atomicAdd(&g_tmpR[r], 1);
        int t1 = (p1 % EPT) * NPIX + (p1 / EPT);
        g_pairRT[t1] = make_int2(c, vb);
        g_ridRT[t1] = r;
        int p2 = g_ptrC[c] + atomicAdd(&g_tmpC[c], 1);
        int t2 = (p2 % EPT) * NPIX + (p2 / EPT);
        g_pairCT[t2] = make_int2(r, vb);
        g_cidCT[t2] = c;
    }
    gbar(ep);

    // ---- loop invariants
    const float rc = g_rs_cm[gtid];
    const float Di = g_D[gtid];
    float p_reg = 0.f, s_reg = 0.f, x_reg = 0.f;

    // ---- CG iterations (single-reduction Chronopoulos-Gear)
    for (int it = 0; it < CG_STEPS; ++it) {
        // Phase 1: entry-centric CSR products -> LA.y; LA.x = rs*r; matting
        {
            double dG = (double)r_reg * (double)r_reg;
            double dDm = 0.0;
            {
                float racc = 0.f;
                int currow = g_ridRT[gtid];   // j = 0 row
                #pragma unroll
                for (int j = 0; j < EPT; j++) {
                    int2 e = g_pairRT[j * NPIX + gtid];
                    int rr = g_ridRT[j * NPIX + gtid];
                    float prod = __int_as_float(e.y) * g_r[e.x];
                    if (rr != currow) {
                        atomicAdd(((float*)&g_LA[currow]) + 1, racc);
                        racc = 0.f; currow = rr;
                    }
                    racc += prod;
                }
                atomicAdd(((float*)&g_LA[currow]) + 1, racc);
                ((float*)&g_LA[gtid])[0] = rc * r_reg;
            }
            if (tid < MPB) {
                int ind = locInd[m];
                float pn[9], acc9[9];
                #pragma unroll
                for (int j = 0; j < 9; j++) { pn[j] = g_r[ind + OFF9(j)]; acc9[j] = 0.f; }
                #pragma unroll
                for (int i9 = 0; i9 < 9; i9++) {
                    #pragma unroll
                    for (int j9 = i9; j9 < 9; j9++) {
                        float v = g_S45[TIDX(i9, j9) * NLOC + m];
                        acc9[i9] += v * pn[j9];
                        if (j9 > i9) acc9[j9] += v * pn[i9];
                    }
                }
                #pragma unroll
                for (int i9 = 0; i9 < 9; i9++) {
                    atomicAdd(&g_w[ind + OFF9(i9)], -acc9[i9]);
                    dDm -= (double)acc9[i9] * (double)pn[i9];
                }
            }
            double2 gd = bred2(dG, dDm, sm2);
            if (tid == 0) g_dot1[blockIdx.x] = gd;
        }
        gbar(ep);

        // Phase 2: entry-centric CSC with Lv = LA.x - LA.y; base; IU
        {
            double dD = 0.0;
            {
                float cacc = 0.f;
                int curcol = g_cidCT[gtid];   // j = 0 col
                #pragma unroll
                for (int j = 0; j < EPT; j++) {
                    int2 e = g_pairCT[j * NPIX + gtid];
                    int cc = g_cidCT[j * NPIX + gtid];
                    float2 la = g_LA[e.x];
                    float prod = __int_as_float(e.y) * (la.x - la.y);
                    if (cc != curcol) {
                        atomicAdd(&g_w[curcol], -cacc);
                        dD -= (double)cacc * (double)g_r[curcol];
                        cacc = 0.f; curcol = cc;
                    }
                    cacc += prod;
                }
                atomicAdd(&g_w[curcol], -cacc);
                dD -= (double)cacc * (double)g_r[curcol];
                // own-pixel base: rs*Lv + D*r
                float2 lai = g_LA[gtid];
                float lvi = lai.x - lai.y;
                float basew = rc * lvi + Di * r_reg;
                atomicAdd(&g_w[gtid], basew);
                dD += (double)r_reg * (double)basew;
            }
            if (tid < MPB) {
                int ind2 = iuInd[m];
                float rind = g_r[ind2];
                float acc2 = 0.f;
                #pragma unroll
                for (int l = 0; l < KIU; l++) {
                    float wv = g_Wiu[l * NLOC + m];
                    int nb   = g_iuNbT[l * NLOC + m];
                    float rnb = g_r[nb];
                    acc2 += wv * rnb;
                    atomicAdd(&g_w[nb], -wv * rind);
                    dD -= (double)(wv * rind) * (double)rnb;
                }
                atomicAdd(&g_w[ind2], -acc2);
                dD -= (double)acc2 * (double)rind;
            }
            dD = bred(dD, sred);
            if (tid == 0) g_dot2[blockIdx.x] = dD;
        }
        gbar(ep);

        // Phase U: reduce; alpha/beta; register update; reset accumulators
        {
            double gamma = 0.0, delta = 0.0;
            if (tid < NBLK) {
                double2 gd = g_dot1[tid];
                gamma = gd.x;
                delta = gd.y + g_dot2[tid];
            }
            double2 gd = bred2(gamma, delta, sm2);
            if (tid == 0) {
                gamma = gd.x; delta = gd.y;
                double beta, alpha;
                if (it == 0) {
                    beta = 0.0;
                    alpha = gamma / delta;
                } else {
                    beta = gamma / s_gamma_prev;
                    alpha = gamma / (delta - beta * gamma / s_alpha_prev);
                }
                s_alpha = alpha; s_beta = beta;
                s_gamma_prev = gamma; s_alpha_prev = alpha;
            }
            __syncthreads();
            float alpha = (float)s_alpha;
            float beta  = (float)s_beta;
            float wi = g_w[gtid];
            g_w[gtid] = 0.f;                       // reset for next iter/replay
            ((float*)&g_LA[gtid])[1] = 0.f;        // reset CSR accumulator
            if (it == 0) { p_reg = r_reg; s_reg = wi; }
            else {
                p_reg = r_reg + beta * p_reg;
                s_reg = wi + beta * s_reg;
            }
            x_reg += alpha * p_reg;
            r_reg = r_reg - alpha * s_reg;
            g_r[gtid] = r_reg;
            if (it == CG_STEPS - 1) x[gtid] = x_reg;
        }
        if (it + 1 < CG_STEPS) gbar(ep);
    }

    // ---- exit: last block resets barrier sense for the next graph replay
    __syncthreads();
    if (tid == 0) {
        __threadfence();
        if (atomicAdd(&g_exit, 1u) == NBLK - 1) {
            g_exit = 0u;
            g_sense = 0u;
            __threadfence();
        }
    }
}

// ---------------- host launch ----------------
extern "C" void kernel_launch(void* const* d_in, const int* in_sizes, int n_in,
                              void* d_out, int out_size) {
    const float* CMw    = (const float*)d_in[0];
    const float* LOCw   = (const float*)d_in[1];
    const float* IUw    = (const float*)d_in[2];
    const float* KUw    = (const float*)d_in[3];
    const float* lmbda  = (const float*)d_in[4];
    const float* kToUcf = (const float*)d_in[5];
    const float* known  = (const float*)d_in[6];
    const float* kToU   = (const float*)d_in[7];
    const float* Wd     = (const float*)d_in[8];
    const float* LF     = (const float*)d_in[9];
    const float* IUf    = (const float*)d_in[10];
    const int*   wrow   = (const int*)d_in[11];
    const int*   wcol   = (const int*)d_in[12];
    const int*   locInd = (const int*)d_in[13];
    const int*   iuInd  = (const int*)d_in[14];
    const int*   iuNb   = (const int*)d_in[15];
    float* x = (float*)d_out;

    k_all<<<NBLK, TPB>>>(x, CMw, LOCw, IUw, KUw, lmbda, kToUcf, known, kToU,
                         Wd, LF, IUf, wrow, wcol, locInd, iuInd, iuNb);
}